// round 16
// baseline (speedup 1.0000x reference)
#include <cuda_runtime.h>
#include <cuda_bf16.h>
#include <mma.h>
#include <math.h>
#include <stdint.h>

using namespace nvcuda;

#define N_IMG  64
#define S_TOK  2602
#define NPATCH 2601
#define E_DIM  128
#define E3     384
#define KPAD   76
#define NROWS  (N_IMG * S_TOK)     // 166528 = 2602*64
#define ASTR   136                 // bf16 smem row stride (pad 8)

extern __shared__ char smraw[];

// ======================= helpers =======================
__device__ __forceinline__ uint64_t pack2(float x, float y) {
    uint64_t r; asm("mov.b64 %0,{%1,%2};" : "=l"(r) : "f"(x), "f"(y)); return r;
}
__device__ __forceinline__ void unpack2(uint64_t v, float& x, float& y) {
    asm("mov.b64 {%0,%1},%2;" : "=f"(x), "=f"(y) : "l"(v));
}
#define FMA2(d, a, b, c) asm("fma.rn.f32x2 %0,%1,%2,%3;" : "=l"(d) : "l"(a), "l"(b), "l"(c))
#define ADD2(d, a, b)    asm("add.rn.f32x2 %0,%1,%2;"    : "=l"(d) : "l"(a), "l"(b))

// ======================= scratch =======================
__device__ __align__(16) __nv_bfloat16 g_x_h[(size_t)NROWS * E_DIM];
__device__ __align__(16) __nv_bfloat16 g_x_l[(size_t)NROWS * E_DIM];
__device__ __align__(16) float         g_qkv[(size_t)NROWS * E3];   // NOTE: no bias (added in attn)
__device__ __align__(16) __nv_bfloat16 g_o_h[(size_t)NROWS * E_DIM];
__device__ __align__(16) __nv_bfloat16 g_o_l[(size_t)NROWS * E_DIM];
__device__ __align__(16) __nv_bfloat16 g_win_h[E3 * E_DIM];   // [n][k]
__device__ __align__(16) __nv_bfloat16 g_win_l[E3 * E_DIM];
__device__ __align__(16) __nv_bfloat16 g_wout_h[E_DIM * E_DIM];
__device__ __align__(16) __nv_bfloat16 g_wout_l[E_DIM * E_DIM];
__device__ float g_pe[S_TOK * E_DIM];
__device__ float g_lmwT[KPAD * E_DIM];
__device__ float g_pooled[N_IMG * E_DIM];

__device__ __forceinline__ void split2(float x, float y, __nv_bfloat162* hp, __nv_bfloat162* lp) {
    __nv_bfloat162 h = __float22bfloat162_rn(make_float2(x, y));
    float rx = x - __low2float(h), ry = y - __high2float(h);
    *hp = h;
    *lp = __float22bfloat162_rn(make_float2(rx, ry));
}

// copy rows x 128-col bf16 tile (row-major, stride 128) into smem stride ASTR
template<int NTHR>
__device__ __forceinline__ void stageR(__nv_bfloat16* dst, const __nv_bfloat16* src,
                                       int tid, int rows) {
    int nv = rows * 16;
    for (int i = tid; i < nv; i += NTHR) {
        int row = i >> 4, c = i & 15;
        *(uint4*)&dst[row * ASTR + c * 8] = *(const uint4*)&src[row * 128 + c * 8];
    }
}
// 256-thread 128-row variant (R12/R15 proven)
__device__ __forceinline__ void stage136(__nv_bfloat16* dst, const __nv_bfloat16* src, int tid) {
    #pragma unroll
    for (int it = 0; it < 8; ++it) {
        int i = tid + it * 256;
        int row = i >> 4, c = i & 15;
        *(uint4*)&dst[row * ASTR + c * 8] = *(const uint4*)&src[row * 128 + c * 8];
    }
}

// ======================= prep (weights + pe + cls + zero, one launch) =======================
__global__ void k_prep(const float* __restrict__ lm_w,
                       const float* __restrict__ w_in,
                       const float* __restrict__ w_out,
                       const float* __restrict__ cls_tok) {
    int bid = blockIdx.x;
    if (bid < S_TOK) {
        int s = bid, e = threadIdx.x;
        if (e < 128) {
            int je = e & ~1;
            float scale = exp2f((float)je * (-13.287712379549449f / 128.0f));
            float ang = (float)s * scale;
            g_pe[s * E_DIM + e] = (e & 1) ? cosf(ang) : sinf(ang);
            if (s < N_IMG) {
                float v = cls_tok[e] + ((e & 1) ? 1.0f : 0.0f);
                __nv_bfloat16 h = __float2bfloat16(v);
                size_t idx = (size_t)(s * S_TOK) * E_DIM + e;
                g_x_h[idx] = h;
                g_x_l[idx] = __float2bfloat16(v - __bfloat162float(h));
            } else if (s < 2 * N_IMG) {
                g_pooled[(s - N_IMG) * E_DIM + e] = 0.0f;
            }
        }
        return;
    }
    int t = (bid - S_TOK) * blockDim.x + threadIdx.x;
    int n = 96 * blockDim.x;
    for (int i = t; i < KPAD * E_DIM; i += n) {
        int k = i / E_DIM, e = i % E_DIM;
        g_lmwT[i] = (k < 75) ? lm_w[e * 75 + k] : 0.0f;
    }
    for (int i = t; i < E3 * E_DIM; i += n) {
        float v = w_in[i];
        __nv_bfloat16 h = __float2bfloat16(v);
        g_win_h[i] = h;
        g_win_l[i] = __float2bfloat16(v - __bfloat162float(h));
    }
    for (int i = t; i < E_DIM * E_DIM; i += n) {
        float v = w_out[i];
        __nv_bfloat16 h = __float2bfloat16(v);
        g_wout_h[i] = h;
        g_wout_l[i] = __float2bfloat16(v - __bfloat162float(h));
    }
}

// ======================= fused patchify + embed (FFMA f32x2, 256 thr) =======================
#define EMB_SMEM ((64 * KPAD + KPAD * E_DIM) * 4)

__global__ __launch_bounds__(256) void k_embed(const float* __restrict__ images,
                                               const float* __restrict__ lm_b) {
    float* smf = (float*)smraw;
    float* As = smf;               // [64][76]
    float* Bs = smf + 64 * KPAD;   // [76][128]
    const int b  = blockIdx.y;
    const int p0 = blockIdx.x * 64;
    const int tid = threadIdx.x;

    for (int i = tid; i < KPAD * E_DIM; i += 256) Bs[i] = g_lmwT[i];
    for (int i = tid; i < 64 * KPAD; i += 256) {
        int m = i / KPAD, k = i % KPAD;
        int p = p0 + m;
        float v = 0.0f;
        if (k < 75 && p < NPATCH) {
            int c = k / 25, r = k % 25, ph = r / 5, pw = r % 5;
            int ii = p / 51, jj = p % 51;
            v = images[((b * 3 + c) * 255 + (ii * 5 + ph)) * 255 + (jj * 5 + pw)];
        }
        As[i] = v;
    }
    __syncthreads();

    const int tx = tid & 15, ty = tid >> 4;
    uint64_t acc2[4][4];
    {
        uint64_t z = pack2(0.f, 0.f);
        #pragma unroll
        for (int i = 0; i < 4; i++)
            #pragma unroll
            for (int j = 0; j < 4; j++) acc2[i][j] = z;
    }

    #pragma unroll 1
    for (int k = 0; k < KPAD; k += 4) {
        float4 av[4];
        #pragma unroll
        for (int i = 0; i < 4; i++)
            av[i] = *(const float4*)&As[(ty * 4 + i) * KPAD + k];
        #pragma unroll
        for (int kk = 0; kk < 4; kk++) {
            float4 b0 = *(const float4*)&Bs[(k + kk) * E_DIM + tx * 4];
            float4 b1 = *(const float4*)&Bs[(k + kk) * E_DIM + 64 + tx * 4];
            uint64_t bb2[4] = {pack2(b0.x, b0.y), pack2(b0.z, b0.w),
                               pack2(b1.x, b1.y), pack2(b1.z, b1.w)};
            #pragma unroll
            for (int i = 0; i < 4; i++) {
                float a = ((const float*)&av[i])[kk];
                uint64_t aa = pack2(a, a);
                #pragma unroll
                for (int j = 0; j < 4; j++) FMA2(acc2[i][j], aa, bb2[j], acc2[i][j]);
            }
        }
    }

    #pragma unroll
    for (int i = 0; i < 4; i++) {
        int p = p0 + ty * 4 + i;
        if (p >= NPATCH) continue;
        int s = 1 + p;
        size_t base = ((size_t)b * S_TOK + s) * E_DIM;
        #pragma unroll
        for (int half = 0; half < 2; half++) {
            int col = half * 64 + tx * 4;
            float x0, y0, x1, y1;
            unpack2(acc2[i][half * 2],     x0, y0);
            unpack2(acc2[i][half * 2 + 1], x1, y1);
            float vx = x0 + lm_b[col+0] + g_pe[s * E_DIM + col + 0];
            float vy = y0 + lm_b[col+1] + g_pe[s * E_DIM + col + 1];
            float vz = x1 + lm_b[col+2] + g_pe[s * E_DIM + col + 2];
            float vw = y1 + lm_b[col+3] + g_pe[s * E_DIM + col + 3];
            __nv_bfloat162 h0, l0, h1, l1;
            split2(vx, vy, &h0, &l0);
            split2(vz, vw, &h1, &l1);
            *(__nv_bfloat162*)&g_x_h[base + col]     = h0;
            *(__nv_bfloat162*)&g_x_h[base + col + 2] = h1;
            *(__nv_bfloat162*)&g_x_l[base + col]     = l0;
            *(__nv_bfloat162*)&g_x_l[base + col + 2] = l1;
        }
    }
}

// ======= QKV GEMM: persistent, B resident, M=64 A tiles, 2 CTAs/SM (no bias) =======
#define Q2_BH  0
#define Q2_BL  (128 * ASTR)
#define Q2_AH  (2 * 128 * ASTR)
#define Q2_AL  (Q2_AH + 64 * ASTR)
#define Q2_NBF (Q2_AL + 64 * ASTR)          // 52224 bf16
#define Q2_SMEM (Q2_NBF * 2)                // 104448 bytes -> 2 CTAs/SM

#define NMT64 2602   // number of 64-row m-tiles
#define SLOTS 296    // 148 SMs * 2 CTAs

__global__ __launch_bounds__(256, 2) void k_qkv_p2() {
    __nv_bfloat16* smb = (__nv_bfloat16*)smraw;
    const int tid = threadIdx.x, wid = tid >> 5;
    const int n0 = blockIdx.x * 128;   // 0..2
    const int slot = blockIdx.y;       // 0..295

    // one-time: stage B hi/lo
    stageR<256>(smb + Q2_BH, g_win_h + (size_t)n0 * E_DIM, tid, 128);
    stageR<256>(smb + Q2_BL, g_win_l + (size_t)n0 * E_DIM, tid, 128);

    const int wm = wid & 1, wn = wid >> 1;   // 2 m-warps x 4 n-warps, warp tile 32x32

    #pragma unroll 1
    for (int mt = slot; mt < NMT64; mt += SLOTS) {
        __syncthreads();   // protect A buffer from previous iteration's readers
        stageR<256>(smb + Q2_AH, g_x_h + (size_t)mt * 64 * E_DIM, tid, 64);
        stageR<256>(smb + Q2_AL, g_x_l + (size_t)mt * 64 * E_DIM, tid, 64);
        __syncthreads();

        wmma::fragment<wmma::accumulator, 16, 16, 16, float> c[2][2];
        #pragma unroll
        for (int i = 0; i < 2; i++)
            #pragma unroll
            for (int j = 0; j < 2; j++)
                wmma::fill_fragment(c[i][j], 0.0f);

        #pragma unroll
        for (int pass = 0; pass < 3; pass++) {
            const __nv_bfloat16* Ab = smb + ((pass == 2) ? Q2_AL : Q2_AH);
            const __nv_bfloat16* Bb = smb + ((pass == 1) ? Q2_BL : Q2_BH);
            #pragma unroll 2
            for (int k0 = 0; k0 < 128; k0 += 16) {
                wmma::fragment<wmma::matrix_a, 16, 16, 16, __nv_bfloat16, wmma::row_major> a[2];
                wmma::fragment<wmma::matrix_b, 16, 16, 16, __nv_bfloat16, wmma::col_major> b[2];
                #pragma unroll
                for (int i = 0; i < 2; i++)
                    wmma::load_matrix_sync(a[i], &Ab[(wm * 32 + i * 16) * ASTR + k0], ASTR);
                #pragma unroll
                for (int j = 0; j < 2; j++)
                    wmma::load_matrix_sync(b[j], &Bb[(wn * 32 + j * 16) * ASTR + k0], ASTR);
                #pragma unroll
                for (int i = 0; i < 2; i++)
                    #pragma unroll
                    for (int j = 0; j < 2; j++)
                        wmma::mma_sync(c[i][j], a[i], b[j], c[i][j]);
            }
        }

        #pragma unroll
        for (int i = 0; i < 2; i++)
            #pragma unroll
            for (int j = 0; j < 2; j++)
                wmma::store_matrix_sync(
                    &g_qkv[(size_t)(mt * 64 + wm * 32 + i * 16) * E3 + n0 + wn * 32 + j * 16],
                    c[i][j], E3, wmma::mem_row_major);
    }
}

// ======================= attention: single-pass max-free softmax (+qkv bias) =======================
__global__ __launch_bounds__(512, 2) void k_attn(const float* __restrict__ b_in) {
    float* smf = (float*)smraw;      // [64][384] qkv for this token (bias added on load)
    const int s = blockIdx.x, tid = threadIdx.x;

    for (int i = tid; i < 64 * 96; i += 512) {
        int b = i / 96, j = i % 96;
        float4 v = *(const float4*)&g_qkv[((size_t)b * S_TOK + s) * E3 + j * 4];
        float4 bb = *(const float4*)&b_in[j * 4];
        v.x += bb.x; v.y += bb.y; v.z += bb.z; v.w += bb.w;
        ((float4*)smf)[i] = v;
    }
    __syncthreads();

    const int h = tid >> 6, l = tid & 63;
    uint64_t q2[8];
    {
        const float4* qp4 = (const float4*)&smf[l * E3 + h * 16];
        #pragma unroll
        for (int d = 0; d < 4; d++) {
            float4 q = qp4[d];
            q2[2*d]   = pack2(q.x * 0.25f, q.y * 0.25f);
            q2[2*d+1] = pack2(q.z * 0.25f, q.w * 0.25f);
        }
    }

    uint64_t o2[8];
    {
        uint64_t z = pack2(0.f, 0.f);
        #pragma unroll
        for (int d = 0; d < 8; d++) o2[d] = z;
    }
    float sum = 0.f;

    #pragma unroll 2
    for (int m = 0; m < 64; m++) {
        const float4* kp4 = (const float4*)&smf[m * E3 + 128 + h * 16];
        float4 ka = kp4[0], kb = kp4[1], kc = kp4[2], kd = kp4[3];
        uint64_t a0, a1, a2, a3;
        uint64_t z = pack2(0.f, 0.f);
        FMA2(a0, q2[0], pack2(ka.x, ka.y), z);
        FMA2(a1, q2[1], pack2(ka.z, ka.w), z);
        FMA2(a2, q2[2], pack2(kb.x, kb.y), z);
        FMA2(a3, q2[3], pack2(kb.z, kb.w), z);
        FMA2(a0, q2[4], pack2(kc.x, kc.y), a0);
        FMA2(a1, q2[5], pack2(kc.z, kc.w), a1);
        FMA2(a2, q2[6], pack2(kd.x, kd.y), a2);
        FMA2(a3, q2[7], pack2(kd.z, kd.w), a3);
        ADD2(a0, a0, a1);
        ADD2(a2, a2, a3);
        ADD2(a0, a0, a2);
        float x, y;
        unpack2(a0, x, y);
        float e = __expf(x + y);
        sum += e;
        uint64_t w2 = pack2(e, e);
        const float4* vp4 = (const float4*)&smf[m * E3 + 256 + h * 16];
        float4 va = vp4[0], vb = vp4[1], vc = vp4[2], vd = vp4[3];
        FMA2(o2[0], pack2(va.x, va.y), w2, o2[0]);
        FMA2(o2[1], pack2(va.z, va.w), w2, o2[1]);
        FMA2(o2[2], pack2(vb.x, vb.y), w2, o2[2]);
        FMA2(o2[3], pack2(vb.z, vb.w), w2, o2[3]);
        FMA2(o2[4], pack2(vc.x, vc.y), w2, o2[4]);
        FMA2(o2[5], pack2(vc.z, vc.w), w2, o2[5]);
        FMA2(o2[6], pack2(vd.x, vd.y), w2, o2[6]);
        FMA2(o2[7], pack2(vd.z, vd.w), w2, o2[7]);
    }

    const float inv = 1.0f / sum;
    size_t base = ((size_t)l * S_TOK + s) * E_DIM + h * 16;
    __nv_bfloat162* oh = (__nv_bfloat162*)&g_o_h[base];
    __nv_bfloat162* ol = (__nv_bfloat162*)&g_o_l[base];
    #pragma unroll
    for (int d = 0; d < 8; d++) {
        float x, y;
        unpack2(o2[d], x, y);
        __nv_bfloat162 hh, ll;
        split2(x * inv, y * inv, &hh, &ll);
        oh[d] = hh;
        ol[d] = ll;
    }
}

// ======================= out-proj GEMM + LN + pool (wmma, round-12 exact) =======================
#define OW_AH 0
#define OW_AL (128 * ASTR)
#define OW_BH (2 * 128 * ASTR)
#define OW_BL (3 * 128 * ASTR)
#define OW_NBF (4 * 128 * ASTR)
#define OW_C    (OW_NBF * 2)
#define OW_BIAS (OW_C + 128 * 132 * 4)
#define OW_MU   (OW_BIAS + 16 * 132 * 4)
#define OW_RSD  (OW_MU + 512)
#define OW_SMEM (OW_RSD + 512)

__global__ __launch_bounds__(256) void k_out_w(const float* __restrict__ b_out,
                                               const float* __restrict__ ln_g,
                                               const float* __restrict__ ln_b) {
    __nv_bfloat16* smb = (__nv_bfloat16*)smraw;
    float* Cs    = (float*)(smraw + OW_C);
    float* sBias = (float*)(smraw + OW_BIAS);
    float* sMu   = (float*)(smraw + OW_MU);
    float* sRsd  = (float*)(smraw + OW_RSD);
    const int tid = threadIdx.x, wid = tid >> 5;
    const int m0 = blockIdx.x * 128;

    stage136(smb + OW_AH, g_o_h + (size_t)m0 * E_DIM, tid);
    stage136(smb + OW_AL, g_o_l + (size_t)m0 * E_DIM, tid);
    stage136(smb + OW_BH, g_wout_h, tid);
    stage136(smb + OW_BL, g_wout_l, tid);
    for (int i = tid; i < 16 * 132; i += 256) sBias[i] = b_out[(i % 132 < 128 ? i % 132 : 0)];
    __syncthreads();

    const int wm = wid & 3, wn = wid >> 2;
    wmma::fragment<wmma::accumulator, 16, 16, 16, float> c[2][4];
    #pragma unroll
    for (int i = 0; i < 2; i++)
        #pragma unroll
        for (int j = 0; j < 4; j++)
            wmma::load_matrix_sync(c[i][j], &sBias[wn * 64 + j * 16], 132, wmma::mem_row_major);

    #pragma unroll
    for (int pass = 0; pass < 3; pass++) {
        const __nv_bfloat16* Ab = smb + (pass == 2 ? OW_AL : OW_AH);
        const __nv_bfloat16* Bb = smb + (pass == 1 ? OW_BL : OW_BH);
        #pragma unroll
        for (int k0 = 0; k0 < 128; k0 += 16) {
            wmma::fragment<wmma::matrix_a, 16, 16, 16, __nv_bfloat16, wmma::row_major> a[2];
            wmma::fragment<wmma::matrix_b, 16, 16, 16, __nv_bfloat16, wmma::col_major> b[4];
            #pragma unroll
            for (int i = 0; i < 2; i++)
                wmma::load_matrix_sync(a[i], &Ab[(wm * 32 + i * 16) * ASTR + k0], ASTR);
            #pragma unroll
            for (int j = 0; j < 4; j++)
                wmma::load_matrix_sync(b[j], &Bb[(wn * 64 + j * 16) * ASTR + k0], ASTR);
            #pragma unroll
            for (int i = 0; i < 2; i++)
                #pragma unroll
                for (int j = 0; j < 4; j++)
                    wmma::mma_sync(c[i][j], a[i], b[j], c[i][j]);
        }
    }

    #pragma unroll
    for (int i = 0; i < 2; i++)
        #pragma unroll
        for (int j = 0; j < 4; j++)
            wmma::store_matrix_sync(&Cs[(wm * 32 + i * 16) * 132 + wn * 64 + j * 16],
                                    c[i][j], 132, wmma::mem_row_major);
    __syncthreads();

    if (tid < 128) {
        const float* row = &Cs[tid * 132];
        float s1 = 0.f;
        #pragma unroll 8
        for (int j = 0; j < 128; j++) s1 += row[j];
        float mu = s1 * (1.0f / 128.0f);
        float s2 = 0.f;
        #pragma unroll 8
        for (int j = 0; j < 128; j++) { float d = row[j] - mu; s2 += d * d; }
        sMu[tid] = mu;
        sRsd[tid] = rsqrtf(s2 * (1.0f / 128.0f) + 1e-5f);
    }
    __syncthreads();

    {
        int col = tid & 127;
        int r = (tid >> 7) * 64;
        float gg = ln_g[col], bb = ln_b[col];
        int b0 = (m0 + r) / S_TOK;
        int boundary = (b0 + 1) * S_TOK - m0;
        float a0 = 0.f, a1 = 0.f;
        #pragma unroll 4
        for (int t = 0; t < 64; t++, r++) {
            float v = (Cs[r * 132 + col] - sMu[r]) * sRsd[r] * gg + bb;
            if (r < boundary) a0 += v; else a1 += v;
        }
        atomicAdd(&g_pooled[b0 * E_DIM + col], a0);
        if (a1 != 0.f || ((tid >> 7) * 64 + 63) >= boundary)
            if (b0 + 1 < N_IMG) atomicAdd(&g_pooled[(b0 + 1) * E_DIM + col], a1);
    }
}

// ======================= classifier head =======================
__global__ void k_head(const float* __restrict__ out_w,
                       const float* __restrict__ out_b,
                       float* __restrict__ out) {
    int b = blockIdx.x, tid = threadIdx.x;
    __shared__ float red[3][4];
    float p = g_pooled[b * E_DIM + tid] * (1.0f / (float)S_TOK);
    int lane = tid & 31, w = tid >> 5;
    #pragma unroll
    for (int c = 0; c < 3; c++) {
        float v = p * out_w[c * E_DIM + tid];
        #pragma unroll
        for (int off = 16; off; off >>= 1) v += __shfl_xor_sync(0xffffffffu, v, off);
        if (lane == 0) red[c][w] = v;
    }
    __syncthreads();
    if (tid < 3)
        out[b * 3 + tid] = red[tid][0] + red[tid][1] + red[tid][2] + red[tid][3] + out_b[tid];
}

// ======================= launch =======================
extern "C" void kernel_launch(void* const* d_in, const int* in_sizes, int n_in,
                              void* d_out, int out_size) {
    const float* images  = (const float*)d_in[0];
    const float* lm_w    = (const float*)d_in[1];
    const float* lm_b    = (const float*)d_in[2];
    const float* cls_tok = (const float*)d_in[3];
    const float* w_in    = (const float*)d_in[4];
    const float* b_in    = (const float*)d_in[5];
    const float* w_out   = (const float*)d_in[6];
    const float* b_out   = (const float*)d_in[7];
    const float* ln_g    = (const float*)d_in[8];
    const float* ln_b    = (const float*)d_in[9];
    const float* out_w   = (const float*)d_in[10];
    const float* out_b   = (const float*)d_in[11];
    float* out = (float*)d_out;

    const int SMEM_ATTN = 64 * E3 * 4;

    cudaFuncSetAttribute(k_embed,  cudaFuncAttributeMaxDynamicSharedMemorySize, EMB_SMEM);
    cudaFuncSetAttribute(k_attn,   cudaFuncAttributeMaxDynamicSharedMemorySize, SMEM_ATTN);
    cudaFuncSetAttribute(k_qkv_p2, cudaFuncAttributeMaxDynamicSharedMemorySize, Q2_SMEM);
    cudaFuncSetAttribute(k_out_w,  cudaFuncAttributeMaxDynamicSharedMemorySize, OW_SMEM);

    k_prep<<<S_TOK + 96, 256>>>(lm_w, w_in, w_out, cls_tok);   // launch 1
    k_embed<<<dim3(41, N_IMG), 256, EMB_SMEM>>>(images, lm_b); // launch 2
    k_qkv_p2<<<dim3(3, SLOTS), 256, Q2_SMEM>>>();              // launch 3
    k_attn<<<S_TOK, 512, SMEM_ATTN>>>(b_in);                   // launch 4 -> ncu window
    k_out_w<<<1301, 256, OW_SMEM>>>(b_out, ln_g, ln_b);
    k_head<<<N_IMG, 128>>>(out_w, out_b, out);
}

// round 17
// speedup vs baseline: 1.1089x; 1.1089x over previous
#include <cuda_runtime.h>
#include <cuda_bf16.h>
#include <mma.h>
#include <math.h>
#include <stdint.h>

using namespace nvcuda;

#define N_IMG  64
#define S_TOK  2602
#define NPATCH 2601
#define E_DIM  128
#define E3     384
#define KPAD   76
#define NROWS  (N_IMG * S_TOK)     // 166528 = 1301*128
#define ASTR   136                 // bf16 smem row stride (pad 8)

extern __shared__ char smraw[];

// ======================= helpers =======================
__device__ __forceinline__ uint32_t smem_u32(const void* p) {
    uint32_t a;
    asm("{ .reg .u64 t; cvta.to.shared.u64 t, %1; cvt.u32.u64 %0, t; }" : "=r"(a) : "l"(p));
    return a;
}
#define CP16(sm, gm) asm volatile("cp.async.cg.shared.global [%0], [%1], 16;" :: "r"(sm), "l"(gm))
#define CP_COMMIT()  asm volatile("cp.async.commit_group;" ::: "memory")
#define CP_WAIT0()   asm volatile("cp.async.wait_group 0;" ::: "memory")

__device__ __forceinline__ uint64_t pack2(float x, float y) {
    uint64_t r; asm("mov.b64 %0,{%1,%2};" : "=l"(r) : "f"(x), "f"(y)); return r;
}
__device__ __forceinline__ void unpack2(uint64_t v, float& x, float& y) {
    asm("mov.b64 {%0,%1},%2;" : "=f"(x), "=f"(y) : "l"(v));
}
#define FMA2(d, a, b, c) asm("fma.rn.f32x2 %0,%1,%2,%3;" : "=l"(d) : "l"(a), "l"(b), "l"(c))
#define ADD2(d, a, b)    asm("add.rn.f32x2 %0,%1,%2;"    : "=l"(d) : "l"(a), "l"(b))

// ======================= scratch =======================
__device__ __align__(16) __nv_bfloat16 g_x_h[(size_t)NROWS * E_DIM];
__device__ __align__(16) __nv_bfloat16 g_x_l[(size_t)NROWS * E_DIM];
__device__ __align__(16) float         g_qkv[(size_t)NROWS * E3];
__device__ __align__(16) __nv_bfloat16 g_o_h[(size_t)NROWS * E_DIM];
__device__ __align__(16) __nv_bfloat16 g_o_l[(size_t)NROWS * E_DIM];
__device__ __align__(16) __nv_bfloat16 g_win_h[E3 * E_DIM];   // [n][k]
__device__ __align__(16) __nv_bfloat16 g_win_l[E3 * E_DIM];
__device__ __align__(16) __nv_bfloat16 g_wout_h[E_DIM * E_DIM];
__device__ __align__(16) __nv_bfloat16 g_wout_l[E_DIM * E_DIM];
__device__ float g_pe[S_TOK * E_DIM];
__device__ float g_lmwT[KPAD * E_DIM];
__device__ float g_pooled[N_IMG * E_DIM];

__device__ __forceinline__ void split2(float x, float y, __nv_bfloat162* hp, __nv_bfloat162* lp) {
    __nv_bfloat162 h = __float22bfloat162_rn(make_float2(x, y));
    float rx = x - __low2float(h), ry = y - __high2float(h);
    *hp = h;
    *lp = __float22bfloat162_rn(make_float2(rx, ry));
}

// copy a 128-row x 128-col bf16 tile (row-major, src stride 128) into smem stride ASTR
__device__ __forceinline__ void stage136(__nv_bfloat16* dst, const __nv_bfloat16* src, int tid) {
    #pragma unroll
    for (int it = 0; it < 8; ++it) {
        int i = tid + it * 256;
        int row = i >> 4, c = i & 15;
        *(uint4*)&dst[row * ASTR + c * 8] = *(const uint4*)&src[row * 128 + c * 8];
    }
}
__device__ __forceinline__ void stage136_512(__nv_bfloat16* dst, const __nv_bfloat16* src, int tid) {
    #pragma unroll
    for (int it = 0; it < 4; ++it) {
        int i = tid + it * 512;
        int row = i >> 4, c = i & 15;
        *(uint4*)&dst[row * ASTR + c * 8] = *(const uint4*)&src[row * 128 + c * 8];
    }
}

// ======================= prep (weights + pe + cls + zero, one launch) =======================
__global__ void k_prep(const float* __restrict__ lm_w,
                       const float* __restrict__ w_in,
                       const float* __restrict__ w_out,
                       const float* __restrict__ cls_tok) {
    int bid = blockIdx.x;
    if (bid < S_TOK) {
        int s = bid, e = threadIdx.x;
        if (e < 128) {
            int je = e & ~1;
            float scale = exp2f((float)je * (-13.287712379549449f / 128.0f));
            float ang = (float)s * scale;
            g_pe[s * E_DIM + e] = (e & 1) ? cosf(ang) : sinf(ang);
            if (s < N_IMG) {
                float v = cls_tok[e] + ((e & 1) ? 1.0f : 0.0f);
                __nv_bfloat16 h = __float2bfloat16(v);
                size_t idx = (size_t)(s * S_TOK) * E_DIM + e;
                g_x_h[idx] = h;
                g_x_l[idx] = __float2bfloat16(v - __bfloat162float(h));
            } else if (s < 2 * N_IMG) {
                g_pooled[(s - N_IMG) * E_DIM + e] = 0.0f;
            }
        }
        return;
    }
    int t = (bid - S_TOK) * blockDim.x + threadIdx.x;
    int n = 96 * blockDim.x;
    for (int i = t; i < KPAD * E_DIM; i += n) {
        int k = i / E_DIM, e = i % E_DIM;
        g_lmwT[i] = (k < 75) ? lm_w[e * 75 + k] : 0.0f;
    }
    for (int i = t; i < E3 * E_DIM; i += n) {
        float v = w_in[i];
        __nv_bfloat16 h = __float2bfloat16(v);
        g_win_h[i] = h;
        g_win_l[i] = __float2bfloat16(v - __bfloat162float(h));
    }
    for (int i = t; i < E_DIM * E_DIM; i += n) {
        float v = w_out[i];
        __nv_bfloat16 h = __float2bfloat16(v);
        g_wout_h[i] = h;
        g_wout_l[i] = __float2bfloat16(v - __bfloat162float(h));
    }
}

// ======================= fused patchify + embed (FFMA f32x2, 256 thr) =======================
#define EMB_SMEM ((64 * KPAD + KPAD * E_DIM) * 4)

__global__ __launch_bounds__(256) void k_embed(const float* __restrict__ images,
                                               const float* __restrict__ lm_b) {
    float* smf = (float*)smraw;
    float* As = smf;               // [64][76]
    float* Bs = smf + 64 * KPAD;   // [76][128]
    const int b  = blockIdx.y;
    const int p0 = blockIdx.x * 64;
    const int tid = threadIdx.x;

    for (int i = tid; i < KPAD * E_DIM; i += 256) Bs[i] = g_lmwT[i];
    for (int i = tid; i < 64 * KPAD; i += 256) {
        int m = i / KPAD, k = i % KPAD;
        int p = p0 + m;
        float v = 0.0f;
        if (k < 75 && p < NPATCH) {
            int c = k / 25, r = k % 25, ph = r / 5, pw = r % 5;
            int ii = p / 51, jj = p % 51;
            v = images[((b * 3 + c) * 255 + (ii * 5 + ph)) * 255 + (jj * 5 + pw)];
        }
        As[i] = v;
    }
    __syncthreads();

    const int tx = tid & 15, ty = tid >> 4;
    uint64_t acc2[4][4];
    {
        uint64_t z = pack2(0.f, 0.f);
        #pragma unroll
        for (int i = 0; i < 4; i++)
            #pragma unroll
            for (int j = 0; j < 4; j++) acc2[i][j] = z;
    }

    #pragma unroll 1
    for (int k = 0; k < KPAD; k += 4) {
        float4 av[4];
        #pragma unroll
        for (int i = 0; i < 4; i++)
            av[i] = *(const float4*)&As[(ty * 4 + i) * KPAD + k];
        #pragma unroll
        for (int kk = 0; kk < 4; kk++) {
            float4 b0 = *(const float4*)&Bs[(k + kk) * E_DIM + tx * 4];
            float4 b1 = *(const float4*)&Bs[(k + kk) * E_DIM + 64 + tx * 4];
            uint64_t bb2[4] = {pack2(b0.x, b0.y), pack2(b0.z, b0.w),
                               pack2(b1.x, b1.y), pack2(b1.z, b1.w)};
            #pragma unroll
            for (int i = 0; i < 4; i++) {
                float a = ((const float*)&av[i])[kk];
                uint64_t aa = pack2(a, a);
                #pragma unroll
                for (int j = 0; j < 4; j++) FMA2(acc2[i][j], aa, bb2[j], acc2[i][j]);
            }
        }
    }

    #pragma unroll
    for (int i = 0; i < 4; i++) {
        int p = p0 + ty * 4 + i;
        if (p >= NPATCH) continue;
        int s = 1 + p;
        size_t base = ((size_t)b * S_TOK + s) * E_DIM;
        #pragma unroll
        for (int half = 0; half < 2; half++) {
            int col = half * 64 + tx * 4;
            float x0, y0, x1, y1;
            unpack2(acc2[i][half * 2],     x0, y0);
            unpack2(acc2[i][half * 2 + 1], x1, y1);
            float vx = x0 + lm_b[col+0] + g_pe[s * E_DIM + col + 0];
            float vy = y0 + lm_b[col+1] + g_pe[s * E_DIM + col + 1];
            float vz = x1 + lm_b[col+2] + g_pe[s * E_DIM + col + 2];
            float vw = y1 + lm_b[col+3] + g_pe[s * E_DIM + col + 3];
            __nv_bfloat162 h0, l0, h1, l1;
            split2(vx, vy, &h0, &l0);
            split2(vz, vw, &h1, &l1);
            *(__nv_bfloat162*)&g_x_h[base + col]     = h0;
            *(__nv_bfloat162*)&g_x_h[base + col + 2] = h1;
            *(__nv_bfloat162*)&g_x_l[base + col]     = l0;
            *(__nv_bfloat162*)&g_x_l[base + col + 2] = l1;
        }
    }
}

// ======= QKV GEMM: persistent CTAs, B resident, A double-buffered via cp.async (R15) =======
#define QP_BH  0
#define QP_BL  (128 * ASTR)
#define QP_A0H (2 * 128 * ASTR)
#define QP_A0L (3 * 128 * ASTR)
#define QP_A1H (4 * 128 * ASTR)
#define QP_A1L (5 * 128 * ASTR)
#define QP_NBF (6 * 128 * ASTR)                 // 104448 bf16
#define QP_SMEM (QP_NBF * 2 + 16 * 132 * 4)     // 217344 bytes

#define NMT 1301   // number of 128-row m-tiles

__global__ __launch_bounds__(512, 1) void k_qkv_p(const float* __restrict__ b_in) {
    __nv_bfloat16* smb = (__nv_bfloat16*)smraw;
    float* sBias = (float*)(smraw + QP_NBF * 2);
    const int tid = threadIdx.x, wid = tid >> 5;
    const int n0 = blockIdx.x * 128;   // 0..2
    const int slot = blockIdx.y;       // 0..147

    stage136_512(smb + QP_BH, g_win_h + (size_t)n0 * E_DIM, tid);
    stage136_512(smb + QP_BL, g_win_l + (size_t)n0 * E_DIM, tid);
    for (int i = tid; i < 16 * 132; i += 512) sBias[i] = b_in[n0 + (i % 132 < 128 ? i % 132 : 0)];

    const uint32_t aBase[2][2] = {
        { smem_u32(smb + QP_A0H), smem_u32(smb + QP_A0L) },
        { smem_u32(smb + QP_A1H), smem_u32(smb + QP_A1L) } };

    auto stageA = [&](int buf, int mt) {
        size_t g0 = (size_t)mt * 128 * E_DIM;
        #pragma unroll
        for (int it = 0; it < 4; ++it) {
            int i = tid + it * 512;
            int row = i >> 4, c = i & 15;
            uint32_t so = (uint32_t)(row * (ASTR * 2) + c * 16);
            size_t  go = g0 + (size_t)row * 128 + c * 8;
            CP16(aBase[buf][0] + so, g_x_h + go);
            CP16(aBase[buf][1] + so, g_x_l + go);
        }
        CP_COMMIT();
    };

    int mt = slot;
    if (mt < NMT) stageA(0, mt);
    CP_WAIT0();
    __syncthreads();

    const int wm = wid & 3, wn = wid >> 2;   // 4 m-warps x 4 n-warps, warp tile 32x32
    int buf = 0;
    #pragma unroll 1
    for (; mt < NMT; mt += 148) {
        int nxt = mt + 148;
        if (nxt < NMT) stageA(buf ^ 1, nxt);

        const __nv_bfloat16* Ah = smb + (buf ? QP_A1H : QP_A0H);
        const __nv_bfloat16* Al = smb + (buf ? QP_A1L : QP_A0L);

        wmma::fragment<wmma::accumulator, 16, 16, 16, float> c[2][2];
        #pragma unroll
        for (int i = 0; i < 2; i++)
            #pragma unroll
            for (int j = 0; j < 2; j++)
                wmma::load_matrix_sync(c[i][j], &sBias[wn * 32 + j * 16], 132, wmma::mem_row_major);

        #pragma unroll
        for (int pass = 0; pass < 3; pass++) {
            const __nv_bfloat16* Ab = (pass == 2) ? Al : Ah;
            const __nv_bfloat16* Bb = smb + ((pass == 1) ? QP_BL : QP_BH);
            #pragma unroll 2
            for (int k0 = 0; k0 < 128; k0 += 16) {
                wmma::fragment<wmma::matrix_a, 16, 16, 16, __nv_bfloat16, wmma::row_major> a[2];
                wmma::fragment<wmma::matrix_b, 16, 16, 16, __nv_bfloat16, wmma::col_major> b[2];
                #pragma unroll
                for (int i = 0; i < 2; i++)
                    wmma::load_matrix_sync(a[i], &Ab[(wm * 32 + i * 16) * ASTR + k0], ASTR);
                #pragma unroll
                for (int j = 0; j < 2; j++)
                    wmma::load_matrix_sync(b[j], &Bb[(wn * 32 + j * 16) * ASTR + k0], ASTR);
                #pragma unroll
                for (int i = 0; i < 2; i++)
                    #pragma unroll
                    for (int j = 0; j < 2; j++)
                        wmma::mma_sync(c[i][j], a[i], b[j], c[i][j]);
            }
        }

        #pragma unroll
        for (int i = 0; i < 2; i++)
            #pragma unroll
            for (int j = 0; j < 2; j++)
                wmma::store_matrix_sync(
                    &g_qkv[(size_t)(mt * 128 + wm * 32 + i * 16) * E3 + n0 + wn * 32 + j * 16],
                    c[i][j], E3, wmma::mem_row_major);

        if (nxt < NMT) CP_WAIT0();
        __syncthreads();
        buf ^= 1;
    }
}

// ============ attention: warp = head, lane = image pair (halved LDS) ============
__global__ __launch_bounds__(256, 2) void k_attn2() {
    float* smf = (float*)smraw;      // [64][384] qkv for this token
    const int s = blockIdx.x, tid = threadIdx.x;

    for (int i = tid; i < 64 * 96; i += 256) {
        int b = i / 96, j = i % 96;
        ((float4*)smf)[i] = *(const float4*)&g_qkv[((size_t)b * S_TOK + s) * E3 + j * 4];
    }
    __syncthreads();

    const int h = tid >> 5;          // warp = head
    const int l = tid & 31;          // image pair (l, l+32)
    uint64_t qa[8], qb[8];
    {
        const float4* qp4 = (const float4*)&smf[l * E3 + h * 16];
        const float4* qq4 = (const float4*)&smf[(l + 32) * E3 + h * 16];
        #pragma unroll
        for (int d = 0; d < 4; d++) {
            float4 q = qp4[d];
            qa[2*d]   = pack2(q.x * 0.25f, q.y * 0.25f);
            qa[2*d+1] = pack2(q.z * 0.25f, q.w * 0.25f);
            float4 r = qq4[d];
            qb[2*d]   = pack2(r.x * 0.25f, r.y * 0.25f);
            qb[2*d+1] = pack2(r.z * 0.25f, r.w * 0.25f);
        }
    }

    uint64_t oa[8], ob[8];
    {
        uint64_t z = pack2(0.f, 0.f);
        #pragma unroll
        for (int d = 0; d < 8; d++) { oa[d] = z; ob[d] = z; }
    }
    float suma = 0.f, sumb = 0.f;

    #pragma unroll 1
    for (int m = 0; m < 64; m++) {
        const float4* kp4 = (const float4*)&smf[m * E3 + 128 + h * 16];
        float4 ka = kp4[0], kb = kp4[1], kc = kp4[2], kd = kp4[3];
        uint64_t k2[8] = { pack2(ka.x, ka.y), pack2(ka.z, ka.w),
                           pack2(kb.x, kb.y), pack2(kb.z, kb.w),
                           pack2(kc.x, kc.y), pack2(kc.z, kc.w),
                           pack2(kd.x, kd.y), pack2(kd.z, kd.w) };
        uint64_t z = pack2(0.f, 0.f);
        uint64_t a0, a1, b0, b1;
        FMA2(a0, qa[0], k2[0], z);  FMA2(a1, qa[1], k2[1], z);
        FMA2(b0, qb[0], k2[0], z);  FMA2(b1, qb[1], k2[1], z);
        FMA2(a0, qa[2], k2[2], a0); FMA2(a1, qa[3], k2[3], a1);
        FMA2(b0, qb[2], k2[2], b0); FMA2(b1, qb[3], k2[3], b1);
        FMA2(a0, qa[4], k2[4], a0); FMA2(a1, qa[5], k2[5], a1);
        FMA2(b0, qb[4], k2[4], b0); FMA2(b1, qb[5], k2[5], b1);
        FMA2(a0, qa[6], k2[6], a0); FMA2(a1, qa[7], k2[7], a1);
        FMA2(b0, qb[6], k2[6], b0); FMA2(b1, qb[7], k2[7], b1);
        ADD2(a0, a0, a1);
        ADD2(b0, b0, b1);
        float xa, ya, xb, yb;
        unpack2(a0, xa, ya);
        unpack2(b0, xb, yb);
        float ea = __expf(xa + ya);
        float eb = __expf(xb + yb);
        suma += ea;
        sumb += eb;
        uint64_t wa = pack2(ea, ea), wb = pack2(eb, eb);
        const float4* vp4 = (const float4*)&smf[m * E3 + 256 + h * 16];
        float4 va = vp4[0], vb = vp4[1], vc = vp4[2], vd = vp4[3];
        uint64_t v2[8] = { pack2(va.x, va.y), pack2(va.z, va.w),
                           pack2(vb.x, vb.y), pack2(vb.z, vb.w),
                           pack2(vc.x, vc.y), pack2(vc.z, vc.w),
                           pack2(vd.x, vd.y), pack2(vd.z, vd.w) };
        #pragma unroll
        for (int d = 0; d < 8; d++) {
            FMA2(oa[d], v2[d], wa, oa[d]);
            FMA2(ob[d], v2[d], wb, ob[d]);
        }
    }

    const float inva = 1.0f / suma;
    const float invb = 1.0f / sumb;
    {
        size_t base = ((size_t)l * S_TOK + s) * E_DIM + h * 16;
        __nv_bfloat162* oh = (__nv_bfloat162*)&g_o_h[base];
        __nv_bfloat162* ol = (__nv_bfloat162*)&g_o_l[base];
        #pragma unroll
        for (int d = 0; d < 8; d++) {
            float x, y;
            unpack2(oa[d], x, y);
            __nv_bfloat162 hh, ll;
            split2(x * inva, y * inva, &hh, &ll);
            oh[d] = hh;
            ol[d] = ll;
        }
    }
    {
        size_t base = ((size_t)(l + 32) * S_TOK + s) * E_DIM + h * 16;
        __nv_bfloat162* oh = (__nv_bfloat162*)&g_o_h[base];
        __nv_bfloat162* ol = (__nv_bfloat162*)&g_o_l[base];
        #pragma unroll
        for (int d = 0; d < 8; d++) {
            float x, y;
            unpack2(ob[d], x, y);
            __nv_bfloat162 hh, ll;
            split2(x * invb, y * invb, &hh, &ll);
            oh[d] = hh;
            ol[d] = ll;
        }
    }
}

// ======================= out-proj GEMM + LN + pool (wmma, round-12 exact) =======================
#define OW_AH 0
#define OW_AL (128 * ASTR)
#define OW_BH (2 * 128 * ASTR)
#define OW_BL (3 * 128 * ASTR)
#define OW_NBF (4 * 128 * ASTR)
#define OW_C    (OW_NBF * 2)
#define OW_BIAS (OW_C + 128 * 132 * 4)
#define OW_MU   (OW_BIAS + 16 * 132 * 4)
#define OW_RSD  (OW_MU + 512)
#define OW_SMEM (OW_RSD + 512)

__global__ __launch_bounds__(256) void k_out_w(const float* __restrict__ b_out,
                                               const float* __restrict__ ln_g,
                                               const float* __restrict__ ln_b) {
    __nv_bfloat16* smb = (__nv_bfloat16*)smraw;
    float* Cs    = (float*)(smraw + OW_C);
    float* sBias = (float*)(smraw + OW_BIAS);
    float* sMu   = (float*)(smraw + OW_MU);
    float* sRsd  = (float*)(smraw + OW_RSD);
    const int tid = threadIdx.x, wid = tid >> 5;
    const int m0 = blockIdx.x * 128;

    stage136(smb + OW_AH, g_o_h + (size_t)m0 * E_DIM, tid);
    stage136(smb + OW_AL, g_o_l + (size_t)m0 * E_DIM, tid);
    stage136(smb + OW_BH, g_wout_h, tid);
    stage136(smb + OW_BL, g_wout_l, tid);
    for (int i = tid; i < 16 * 132; i += 256) sBias[i] = b_out[(i % 132 < 128 ? i % 132 : 0)];
    __syncthreads();

    const int wm = wid & 3, wn = wid >> 2;
    wmma::fragment<wmma::accumulator, 16, 16, 16, float> c[2][4];
    #pragma unroll
    for (int i = 0; i < 2; i++)
        #pragma unroll
        for (int j = 0; j < 4; j++)
            wmma::load_matrix_sync(c[i][j], &sBias[wn * 64 + j * 16], 132, wmma::mem_row_major);

    #pragma unroll
    for (int pass = 0; pass < 3; pass++) {
        const __nv_bfloat16* Ab = smb + (pass == 2 ? OW_AL : OW_AH);
        const __nv_bfloat16* Bb = smb + (pass == 1 ? OW_BL : OW_BH);
        #pragma unroll
        for (int k0 = 0; k0 < 128; k0 += 16) {
            wmma::fragment<wmma::matrix_a, 16, 16, 16, __nv_bfloat16, wmma::row_major> a[2];
            wmma::fragment<wmma::matrix_b, 16, 16, 16, __nv_bfloat16, wmma::col_major> b[4];
            #pragma unroll
            for (int i = 0; i < 2; i++)
                wmma::load_matrix_sync(a[i], &Ab[(wm * 32 + i * 16) * ASTR + k0], ASTR);
            #pragma unroll
            for (int j = 0; j < 4; j++)
                wmma::load_matrix_sync(b[j], &Bb[(wn * 64 + j * 16) * ASTR + k0], ASTR);
            #pragma unroll
            for (int i = 0; i < 2; i++)
                #pragma unroll
                for (int j = 0; j < 4; j++)
                    wmma::mma_sync(c[i][j], a[i], b[j], c[i][j]);
        }
    }

    #pragma unroll
    for (int i = 0; i < 2; i++)
        #pragma unroll
        for (int j = 0; j < 4; j++)
            wmma::store_matrix_sync(&Cs[(wm * 32 + i * 16) * 132 + wn * 64 + j * 16],
                                    c[i][j], 132, wmma::mem_row_major);
    __syncthreads();

    if (tid < 128) {
        const float* row = &Cs[tid * 132];
        float s1 = 0.f;
        #pragma unroll 8
        for (int j = 0; j < 128; j++) s1 += row[j];
        float mu = s1 * (1.0f / 128.0f);
        float s2 = 0.f;
        #pragma unroll 8
        for (int j = 0; j < 128; j++) { float d = row[j] - mu; s2 += d * d; }
        sMu[tid] = mu;
        sRsd[tid] = rsqrtf(s2 * (1.0f / 128.0f) + 1e-5f);
    }
    __syncthreads();

    {
        int col = tid & 127;
        int r = (tid >> 7) * 64;
        float gg = ln_g[col], bb = ln_b[col];
        int b0 = (m0 + r) / S_TOK;
        int boundary = (b0 + 1) * S_TOK - m0;
        float a0 = 0.f, a1 = 0.f;
        #pragma unroll 4
        for (int t = 0; t < 64; t++, r++) {
            float v = (Cs[r * 132 + col] - sMu[r]) * sRsd[r] * gg + bb;
            if (r < boundary) a0 += v; else a1 += v;
        }
        atomicAdd(&g_pooled[b0 * E_DIM + col], a0);
        if (a1 != 0.f || ((tid >> 7) * 64 + 63) >= boundary)
            if (b0 + 1 < N_IMG) atomicAdd(&g_pooled[(b0 + 1) * E_DIM + col], a1);
    }
}

// ======================= classifier head =======================
__global__ void k_head(const float* __restrict__ out_w,
                       const float* __restrict__ out_b,
                       float* __restrict__ out) {
    int b = blockIdx.x, tid = threadIdx.x;
    __shared__ float red[3][4];
    float p = g_pooled[b * E_DIM + tid] * (1.0f / (float)S_TOK);
    int lane = tid & 31, w = tid >> 5;
    #pragma unroll
    for (int c = 0; c < 3; c++) {
        float v = p * out_w[c * E_DIM + tid];
        #pragma unroll
        for (int off = 16; off; off >>= 1) v += __shfl_xor_sync(0xffffffffu, v, off);
        if (lane == 0) red[c][w] = v;
    }
    __syncthreads();
    if (tid < 3)
        out[b * 3 + tid] = red[tid][0] + red[tid][1] + red[tid][2] + red[tid][3] + out_b[tid];
}

// ======================= launch =======================
extern "C" void kernel_launch(void* const* d_in, const int* in_sizes, int n_in,
                              void* d_out, int out_size) {
    const float* images  = (const float*)d_in[0];
    const float* lm_w    = (const float*)d_in[1];
    const float* lm_b    = (const float*)d_in[2];
    const float* cls_tok = (const float*)d_in[3];
    const float* w_in    = (const float*)d_in[4];
    const float* b_in    = (const float*)d_in[5];
    const float* w_out   = (const float*)d_in[6];
    const float* b_out   = (const float*)d_in[7];
    const float* ln_g    = (const float*)d_in[8];
    const float* ln_b    = (const float*)d_in[9];
    const float* out_w   = (const float*)d_in[10];
    const float* out_b   = (const float*)d_in[11];
    float* out = (float*)d_out;

    const int SMEM_ATTN = 64 * E3 * 4;

    cudaFuncSetAttribute(k_embed, cudaFuncAttributeMaxDynamicSharedMemorySize, EMB_SMEM);
    cudaFuncSetAttribute(k_attn2, cudaFuncAttributeMaxDynamicSharedMemorySize, SMEM_ATTN);
    cudaFuncSetAttribute(k_qkv_p, cudaFuncAttributeMaxDynamicSharedMemorySize, QP_SMEM);
    cudaFuncSetAttribute(k_out_w, cudaFuncAttributeMaxDynamicSharedMemorySize, OW_SMEM);

    k_prep<<<S_TOK + 96, 256>>>(lm_w, w_in, w_out, cls_tok);   // launch 1
    k_embed<<<dim3(41, N_IMG), 256, EMB_SMEM>>>(images, lm_b); // launch 2
    k_qkv_p<<<dim3(3, 148), 512, QP_SMEM>>>(b_in);             // launch 3
    k_attn2<<<S_TOK, 256, SMEM_ATTN>>>();                      // launch 4 -> ncu window
    k_out_w<<<1301, 256, OW_SMEM>>>(b_out, ln_g, ln_b);
    k_head<<<N_IMG, 128>>>(out_w, out_b, out);
}